// round 1
// baseline (speedup 1.0000x reference)
#include <cuda_runtime.h>
#include <cstdint>

#define NN 50000
#define EE 800000

// ---------------- scratch (device globals; no allocation allowed) ----------
__device__ __align__(16) float g_xs[NN * 128];   // transformed features (stride = COUT of layer)
__device__ __align__(16) float g_h[NN * 128];    // aggregated / normalized features
__device__ float g_als[NN];
__device__ float g_ald[NN];
__device__ float g_salpha[EE];
__device__ int   g_deg[NN];
__device__ int   g_off[NN + 1];
__device__ int   g_cur[NN];
__device__ int   g_ssrc[EE];
__device__ int   g_sdst[EE];
__device__ int   g_seid[EE];
__device__ float g_bnsum[128];
__device__ float g_bnsq[128];
__device__ float g_scale[128];
__device__ float g_shift[128];
__device__ float g_ced[8];

// ---------------- f32x2 packed math (sm_100+) ------------------------------
#define FMA2(d, a, b, c) \
    asm("fma.rn.f32x2 %0, %1, %2, %3;" : "=l"(d) : "l"(a), "l"(b), "l"(c))
#define PACK2(d, lo, hi) \
    asm("mov.b64 %0, {%1, %2};" : "=l"(d) : "r"(lo), "r"(hi))
#define UNPACK2(lo, hi, s) \
    asm("mov.b64 {%0, %1}, %2;" : "=r"(lo), "=r"(hi) : "l"(s))

// ---------------- CSR build -------------------------------------------------
__global__ void k_zero_deg() {
    int i = blockIdx.x * blockDim.x + threadIdx.x;
    if (i < NN) g_deg[i] = 0;
}

__global__ void k_hist(const int* __restrict__ dst) {
    int e = blockIdx.x * blockDim.x + threadIdx.x;
    if (e < EE) atomicAdd(&g_deg[dst[e]], 1);
}

// single-block exclusive scan over g_deg -> g_off, g_cur  (1024 threads)
__global__ void k_scan() {
    __shared__ int ws[32];
    __shared__ int carry_s;
    const int tid = threadIdx.x;
    const int lane = tid & 31, wid = tid >> 5;
    if (tid == 0) carry_s = 0;
    __syncthreads();
    for (int base = 0; base < NN; base += 1024) {
        int i = base + tid;
        int v = (i < NN) ? g_deg[i] : 0;
        // warp inclusive scan
        int x = v;
        #pragma unroll
        for (int o = 1; o < 32; o <<= 1) {
            int t = __shfl_up_sync(0xffffffffu, x, o);
            if (lane >= o) x += t;
        }
        if (lane == 31) ws[wid] = x;
        __syncthreads();
        if (wid == 0) {
            int y = ws[lane];
            #pragma unroll
            for (int o = 1; o < 32; o <<= 1) {
                int t = __shfl_up_sync(0xffffffffu, y, o);
                if (lane >= o) y += t;
            }
            ws[lane] = y;
        }
        __syncthreads();
        int warpoff = (wid > 0) ? ws[wid - 1] : 0;
        int incl = carry_s + warpoff + x;
        if (i < NN) {
            g_off[i] = incl - v;
            g_cur[i] = incl - v;
        }
        __syncthreads();
        if (tid == 1023) carry_s = incl;
        __syncthreads();
    }
    if (tid == 0) g_off[NN] = carry_s;
}

__global__ void k_scatter(const int* __restrict__ src, const int* __restrict__ dst) {
    int e = blockIdx.x * blockDim.x + threadIdx.x;
    if (e >= EE) return;
    int d = dst[e];
    int p = atomicAdd(&g_cur[d], 1);
    g_ssrc[p] = src[e];
    g_sdst[p] = d;
    g_seid[p] = e;
}

// ---------------- per-layer kernels ----------------------------------------
// c_edge[j] = sum_c We[j,c] * a_edge[c]
__global__ void k_cedge(const float* __restrict__ We, const float* __restrict__ ae, int C) {
    int j = threadIdx.x;
    if (j < 8) {
        float s = 0.f;
        for (int c = 0; c < C; c++) s += We[j * C + c] * ae[c];
        g_ced[j] = s;
    }
}

// GEMM: Out[N,COUT] = A[N,128] @ W[128,COUT]; block 128 rows, 256 thr, 8x8 micro
template <int COUT>
__launch_bounds__(256)
__global__ void k_gemm(const float* __restrict__ A, const float* __restrict__ W,
                       float* __restrict__ Out) {
    __shared__ float As[128 * 33];
    __shared__ float Bs[32 * 128];
    const int tid = threadIdx.x;
    const int tx = tid & 15, ty = tid >> 4;
    const int row0 = blockIdx.x * 128;

    unsigned long long acc[8][4];
    #pragma unroll
    for (int r = 0; r < 8; r++)
        #pragma unroll
        for (int j = 0; j < 4; j++) acc[r][j] = 0ull;

    for (int k0 = 0; k0 < 128; k0 += 32) {
        // A chunk: 128 rows x 32 cols (float4 per thread-slot)
        #pragma unroll
        for (int t = 0; t < 4; t++) {
            int idx = tid + t * 256;           // 0..1023
            int r = idx >> 3, c4 = (idx & 7) * 4;
            int gr = row0 + r;
            float4 v = (gr < NN) ? *(const float4*)(A + (size_t)gr * 128 + k0 + c4)
                                 : make_float4(0.f, 0.f, 0.f, 0.f);
            float* dp = &As[r * 33 + c4];
            dp[0] = v.x; dp[1] = v.y; dp[2] = v.z; dp[3] = v.w;
        }
        // B chunk: 32 x 128 (zero-padded cols >= COUT)
        #pragma unroll
        for (int t = 0; t < 16; t++) {
            int idx = tid + t * 256;           // 0..4095
            int kk = idx >> 7, c = idx & 127;
            Bs[idx] = (c < COUT) ? W[(size_t)(k0 + kk) * COUT + c] : 0.f;
        }
        __syncthreads();
        #pragma unroll
        for (int kk = 0; kk < 32; kk++) {
            float a[8], b[8];
            #pragma unroll
            for (int r = 0; r < 8; r++) a[r] = As[(ty * 8 + r) * 33 + kk];
            #pragma unroll
            for (int j = 0; j < 8; j++) b[j] = Bs[kk * 128 + tx + 16 * j];
            unsigned long long b2[4];
            #pragma unroll
            for (int j = 0; j < 4; j++)
                PACK2(b2[j], __float_as_uint(b[2 * j]), __float_as_uint(b[2 * j + 1]));
            #pragma unroll
            for (int r = 0; r < 8; r++) {
                unsigned long long a2;
                PACK2(a2, __float_as_uint(a[r]), __float_as_uint(a[r]));
                #pragma unroll
                for (int j = 0; j < 4; j++) FMA2(acc[r][j], a2, b2[j], acc[r][j]);
            }
        }
        __syncthreads();
    }
    #pragma unroll
    for (int r = 0; r < 8; r++) {
        int gr = row0 + ty * 8 + r;
        if (gr >= NN) continue;
        #pragma unroll
        for (int j = 0; j < 4; j++) {
            unsigned lo, hi;
            UNPACK2(lo, hi, acc[r][j]);
            int c0 = tx + 16 * (2 * j), c1 = tx + 16 * (2 * j + 1);
            if (c0 < COUT) Out[(size_t)gr * COUT + c0] = __uint_as_float(lo);
            if (c1 < COUT) Out[(size_t)gr * COUT + c1] = __uint_as_float(hi);
        }
    }
}

// per-node attention logits: al_src = xs . a_src, al_dst = xs . a_dst
template <int C>
__global__ void k_al(const float* __restrict__ asrc, const float* __restrict__ adst) {
    int gw = (blockIdx.x * blockDim.x + threadIdx.x) >> 5;
    int lane = threadIdx.x & 31;
    if (gw >= NN) return;
    const float* xr = g_xs + (size_t)gw * C;
    float s1 = 0.f, s2 = 0.f;
    #pragma unroll
    for (int c = lane; c < C; c += 32) {
        float v = xr[c];
        s1 += v * asrc[c];
        s2 += v * adst[c];
    }
    #pragma unroll
    for (int o = 16; o; o >>= 1) {
        s1 += __shfl_xor_sync(0xffffffffu, s1, o);
        s2 += __shfl_xor_sync(0xffffffffu, s2, o);
    }
    if (lane == 0) { g_als[gw] = s1; g_ald[gw] = s2; }
}

// leaky-relu attention logit per (sorted) edge
__global__ void k_alpha(const float* __restrict__ eatt) {
    int p = blockIdx.x * blockDim.x + threadIdx.x;
    if (p >= EE) return;
    int e = g_seid[p], s = g_ssrc[p], d = g_sdst[p];
    const float4* er = (const float4*)(eatt + (size_t)e * 8);
    float4 e0 = er[0], e1 = er[1];
    float ae = e0.x * g_ced[0] + e0.y * g_ced[1] + e0.z * g_ced[2] + e0.w * g_ced[3]
             + e1.x * g_ced[4] + e1.y * g_ced[5] + e1.z * g_ced[6] + e1.w * g_ced[7];
    float a = g_als[s] + g_ald[d] + ae;
    g_salpha[p] = (a > 0.f) ? a : 0.2f * a;
}

// warp-per-dst-node softmax + weighted gather-accumulate (no atomics)
template <int C>
__global__ void k_agg(const float* __restrict__ bias, float* __restrict__ out) {
    int gw = (blockIdx.x * blockDim.x + threadIdx.x) >> 5;
    int lane = threadIdx.x & 31;
    if (gw >= NN) return;
    int beg = g_off[gw], end = g_off[gw + 1];

    float m = -3.0e38f;
    for (int i = beg + lane; i < end; i += 32) m = fmaxf(m, g_salpha[i]);
    #pragma unroll
    for (int o = 16; o; o >>= 1) m = fmaxf(m, __shfl_xor_sync(0xffffffffu, m, o));

    float den = 0.f;
    for (int i = beg + lane; i < end; i += 32) den += __expf(g_salpha[i] - m);
    #pragma unroll
    for (int o = 16; o; o >>= 1) den += __shfl_xor_sync(0xffffffffu, den, o);
    float inv = (end > beg) ? 1.f / den : 0.f;

    constexpr int NV = C / 4;
    const bool act = lane < NV;
    float4 acc = make_float4(0.f, 0.f, 0.f, 0.f);

    int p = beg;
    for (; p + 2 <= end; p += 2) {
        float a0 = g_salpha[p], a1 = g_salpha[p + 1];
        int s0 = g_ssrc[p], s1 = g_ssrc[p + 1];
        float w0 = __expf(a0 - m) * inv;
        float w1 = __expf(a1 - m) * inv;
        if (act) {
            float4 v0 = *(const float4*)(g_xs + (size_t)s0 * C + lane * 4);
            float4 v1 = *(const float4*)(g_xs + (size_t)s1 * C + lane * 4);
            acc.x += w0 * v0.x + w1 * v1.x;
            acc.y += w0 * v0.y + w1 * v1.y;
            acc.z += w0 * v0.z + w1 * v1.z;
            acc.w += w0 * v0.w + w1 * v1.w;
        }
    }
    if (p < end) {
        float w0 = __expf(g_salpha[p] - m) * inv;
        int s0 = g_ssrc[p];
        if (act) {
            float4 v0 = *(const float4*)(g_xs + (size_t)s0 * C + lane * 4);
            acc.x += w0 * v0.x; acc.y += w0 * v0.y;
            acc.z += w0 * v0.z; acc.w += w0 * v0.w;
        }
    }
    if (act) {
        float4 b = *(const float4*)(bias + lane * 4);
        acc.x += b.x; acc.y += b.y; acc.z += b.z; acc.w += b.w;
        *(float4*)(out + (size_t)gw * C + lane * 4) = acc;
    }
}

// ---------------- batchnorm -------------------------------------------------
__global__ void k_zero_bn() {
    int c = threadIdx.x;
    if (c < 128) { g_bnsum[c] = 0.f; g_bnsq[c] = 0.f; }
}

template <int C>
__global__ void k_bnstat(const float* __restrict__ h) {
    int c = threadIdx.x;
    float s = 0.f, q = 0.f;
    for (int r = blockIdx.x; r < NN; r += gridDim.x) {
        float v = h[(size_t)r * C + c];
        s += v;
        q += v * v;
    }
    atomicAdd(&g_bnsum[c], s);
    atomicAdd(&g_bnsq[c], q);
}

__global__ void k_bnfin(const float* __restrict__ g, const float* __restrict__ b, int C) {
    int c = threadIdx.x;
    if (c < C) {
        float mean = g_bnsum[c] * (1.f / NN);
        float var = g_bnsq[c] * (1.f / NN) - mean * mean;
        float sc = g[c] * rsqrtf(var + 1e-5f);
        g_scale[c] = sc;
        g_shift[c] = b[c] - mean * sc;
    }
}

template <int C, bool RELU>
__global__ void k_bnapply(const float* __restrict__ in, float* __restrict__ out) {
    int r = blockIdx.x, c = threadIdx.x;
    float v = in[(size_t)r * C + c] * g_scale[c] + g_shift[c];
    if (RELU) v = fmaxf(v, 0.f);
    out[(size_t)r * C + c] = v;
}

// ---------------- launch -----------------------------------------------------
extern "C" void kernel_launch(void* const* d_in, const int* in_sizes, int n_in,
                              void* d_out, int out_size) {
    const float* x    = (const float*)d_in[0];
    const int*   ei   = (const int*)d_in[1];
    const float* eatt = (const float*)d_in[2];
    const float* W0   = (const float*)d_in[3];
    const float* as0  = (const float*)d_in[4];
    const float* ad0  = (const float*)d_in[5];
    const float* We0  = (const float*)d_in[6];
    const float* ae0  = (const float*)d_in[7];
    const float* b0   = (const float*)d_in[8];
    const float* W1   = (const float*)d_in[9];
    const float* as1  = (const float*)d_in[10];
    const float* ad1  = (const float*)d_in[11];
    const float* We1  = (const float*)d_in[12];
    const float* ae1  = (const float*)d_in[13];
    const float* b1   = (const float*)d_in[14];
    const float* bng  = (const float*)d_in[15];
    const float* bnb  = (const float*)d_in[16];
    const float* bfg  = (const float*)d_in[17];
    const float* bfb  = (const float*)d_in[18];
    float* out = (float*)d_out;

    const int* src = ei;
    const int* dst = ei + EE;

    float* p_xs = nullptr;
    float* p_h  = nullptr;
    cudaGetSymbolAddress((void**)&p_xs, g_xs);
    cudaGetSymbolAddress((void**)&p_h,  g_h);

    const int TB = 256;
    const int gE = (EE + TB - 1) / TB;
    const int gN = (NN + TB - 1) / TB;
    const int gW = (NN * 32 + TB - 1) / TB;   // warp-per-node grids
    const int gG = (NN + 127) / 128;          // gemm grid

    // ---- CSR by dst (graph fixed; rebuilt every call for determinism rules)
    k_zero_deg<<<gN, TB>>>();
    k_hist<<<gE, TB>>>(dst);
    k_scan<<<1, 1024>>>();
    k_scatter<<<gE, TB>>>(src, dst);

    // ---- layer 0: 128 -> 128
    k_cedge<<<1, 32>>>(We0, ae0, 128);
    k_gemm<128><<<gG, 256>>>(x, W0, p_xs);
    k_al<128><<<gW, TB>>>(as0, ad0);
    k_alpha<<<gE, TB>>>(eatt);
    k_agg<128><<<gW, TB>>>(b0, p_h);
    k_zero_bn<<<1, 128>>>();
    k_bnstat<128><<<512, 128>>>(p_h);
    k_bnfin<<<1, 128>>>(bng, bnb, 128);
    k_bnapply<128, true><<<NN, 128>>>(p_h, p_h);

    // ---- layer 1: 128 -> 112
    k_cedge<<<1, 32>>>(We1, ae1, 112);
    k_gemm<112><<<gG, 256>>>(p_h, W1, p_xs);
    k_al<112><<<gW, TB>>>(as1, ad1);
    k_alpha<<<gE, TB>>>(eatt);
    k_agg<112><<<gW, TB>>>(b1, p_h);
    k_zero_bn<<<1, 128>>>();
    k_bnstat<112><<<512, 112>>>(p_h);
    k_bnfin<<<1, 128>>>(bfg, bfb, 112);
    k_bnapply<112, false><<<NN, 112>>>(p_h, out);
}

// round 2
// speedup vs baseline: 1.1667x; 1.1667x over previous
#include <cuda_runtime.h>
#include <cstdint>

#define NN 50000
#define EE 800000
#define NBLK 49   // ceil(50000/1024)

// ---------------- scratch (device globals) ----------------------------------
__device__ __align__(16) float g_xs[NN * 128];
__device__ __align__(16) float g_h[NN * 128];
__device__ float g_als[NN];
__device__ float g_ald[NN];
__device__ float g_salpha[EE];
__device__ int   g_deg[NN];
__device__ int   g_off[NN + 1];
__device__ int   g_cur[NN];
__device__ int   g_ssrc[EE];
__device__ int   g_pos[EE];
__device__ int   g_bsum[64];
__device__ int   g_boff[64];
__device__ float g_bnacc[512];   // [sum0|sq0|sum1|sq1] x128
__device__ float g_scale[256];   // [0:128) layer0, [128:256) layer1
__device__ float g_shift[256];
__device__ float g_ced[16];      // [0:8) layer0, [8:16) layer1

// ---------------- f32x2 packed math (sm_100+) ------------------------------
#define FMA2(d, a, b, c) \
    asm("fma.rn.f32x2 %0, %1, %2, %3;" : "=l"(d) : "l"(a), "l"(b), "l"(c))
#define PACK2(d, lo, hi) \
    asm("mov.b64 %0, {%1, %2};" : "=l"(d) : "r"(lo), "r"(hi))
#define UNPACK2(lo, hi, s) \
    asm("mov.b64 {%0, %1}, %2;" : "=r"(lo), "=r"(hi) : "l"(s))

// ---------------- init + CSR build ------------------------------------------
__global__ void k_zero() {
    int i = blockIdx.x * blockDim.x + threadIdx.x;
    if (i < NN) g_deg[i] = 0;
    if (i < 512) g_bnacc[i] = 0.f;
}

__global__ void k_hist(const int* __restrict__ dst) {
    int e = blockIdx.x * blockDim.x + threadIdx.x;
    if (e < EE) atomicAdd(&g_deg[dst[e]], 1);
}

__global__ __launch_bounds__(1024) void k_scan_part() {
    __shared__ int ws[32];
    const int tid = threadIdx.x, lane = tid & 31, wid = tid >> 5;
    int i = blockIdx.x * 1024 + tid;
    int v = (i < NN) ? g_deg[i] : 0;
    int x = v;
    #pragma unroll
    for (int o = 1; o < 32; o <<= 1) {
        int t = __shfl_up_sync(0xffffffffu, x, o);
        if (lane >= o) x += t;
    }
    if (lane == 31) ws[wid] = x;
    __syncthreads();
    if (wid == 0) {
        int y = ws[lane];
        #pragma unroll
        for (int o = 1; o < 32; o <<= 1) {
            int t = __shfl_up_sync(0xffffffffu, y, o);
            if (lane >= o) y += t;
        }
        ws[lane] = y;
    }
    __syncthreads();
    int excl = x - v + ((wid > 0) ? ws[wid - 1] : 0);
    if (i < NN) g_off[i] = excl;
    if (tid == 1023) g_bsum[blockIdx.x] = excl + v;
}

__global__ void k_scan_top() {
    if (threadIdx.x == 0) {
        int s = 0;
        for (int i = 0; i < NBLK; i++) { int t = g_bsum[i]; g_boff[i] = s; s += t; }
        g_off[NN] = s;
    }
}

__global__ __launch_bounds__(1024) void k_scan_apply() {
    int i = blockIdx.x * 1024 + threadIdx.x;
    if (i < NN) {
        int o = g_off[i] + g_boff[blockIdx.x];
        g_off[i] = o;
        g_cur[i] = o;
    }
}

__global__ void k_scatter(const int* __restrict__ src, const int* __restrict__ dst) {
    int e = blockIdx.x * blockDim.x + threadIdx.x;
    if (e >= EE) return;
    int p = atomicAdd(&g_cur[dst[e]], 1);
    g_ssrc[p] = src[e];
    g_pos[e] = p;
}

// ---------------- ced for both layers ---------------------------------------
__global__ void k_ced(const float* __restrict__ We0, const float* __restrict__ ae0,
                      const float* __restrict__ We1, const float* __restrict__ ae1) {
    int j = threadIdx.x;
    if (j < 8) {
        float s = 0.f;
        for (int c = 0; c < 128; c++) s += We0[j * 128 + c] * ae0[c];
        g_ced[j] = s;
    } else if (j < 16) {
        int jj = j - 8;
        float s = 0.f;
        for (int c = 0; c < 112; c++) s += We1[jj * 112 + c] * ae1[c];
        g_ced[j] = s;
    }
}

// ---------------- GEMM (+optional BN-relu pre, +al epilogue) ----------------
template <int COUT, bool PRE>
__launch_bounds__(256)
__global__ void k_gemm(const float* __restrict__ A, const float* __restrict__ W,
                       const float* __restrict__ asrc, const float* __restrict__ adst,
                       float* __restrict__ Out) {
    __shared__ float As[128 * 33];
    __shared__ float Bs[32 * 128];
    const int tid = threadIdx.x;
    const int tx = tid & 15, ty = tid >> 4;
    const int row0 = blockIdx.x * 128;

    unsigned long long acc[8][4];
    #pragma unroll
    for (int r = 0; r < 8; r++)
        #pragma unroll
        for (int j = 0; j < 4; j++) acc[r][j] = 0ull;

    for (int k0 = 0; k0 < 128; k0 += 32) {
        #pragma unroll
        for (int t = 0; t < 4; t++) {
            int idx = tid + t * 256;
            int r = idx >> 3, c4 = (idx & 7) * 4;
            int gr = row0 + r;
            float4 v = make_float4(0.f, 0.f, 0.f, 0.f);
            if (gr < NN) {
                v = *(const float4*)(A + (size_t)gr * 128 + k0 + c4);
                if (PRE) {
                    int ch = k0 + c4;
                    v.x = fmaxf(fmaf(v.x, g_scale[ch + 0], g_shift[ch + 0]), 0.f);
                    v.y = fmaxf(fmaf(v.y, g_scale[ch + 1], g_shift[ch + 1]), 0.f);
                    v.z = fmaxf(fmaf(v.z, g_scale[ch + 2], g_shift[ch + 2]), 0.f);
                    v.w = fmaxf(fmaf(v.w, g_scale[ch + 3], g_shift[ch + 3]), 0.f);
                }
            }
            float* dp = &As[r * 33 + c4];
            dp[0] = v.x; dp[1] = v.y; dp[2] = v.z; dp[3] = v.w;
        }
        #pragma unroll
        for (int t = 0; t < 16; t++) {
            int idx = tid + t * 256;
            int kk = idx >> 7, c = idx & 127;
            Bs[idx] = (c < COUT) ? W[(size_t)(k0 + kk) * COUT + c] : 0.f;
        }
        __syncthreads();
        #pragma unroll
        for (int kk = 0; kk < 32; kk++) {
            float a[8], b[8];
            #pragma unroll
            for (int r = 0; r < 8; r++) a[r] = As[(ty * 8 + r) * 33 + kk];
            #pragma unroll
            for (int j = 0; j < 8; j++) b[j] = Bs[kk * 128 + tx + 16 * j];
            unsigned long long b2[4];
            #pragma unroll
            for (int j = 0; j < 4; j++)
                PACK2(b2[j], __float_as_uint(b[2 * j]), __float_as_uint(b[2 * j + 1]));
            #pragma unroll
            for (int r = 0; r < 8; r++) {
                unsigned long long a2;
                PACK2(a2, __float_as_uint(a[r]), __float_as_uint(a[r]));
                #pragma unroll
                for (int j = 0; j < 4; j++) FMA2(acc[r][j], a2, b2[j], acc[r][j]);
            }
        }
        __syncthreads();
    }
    // store + attention-logit epilogue (al_src, al_dst per row)
    #pragma unroll
    for (int r = 0; r < 8; r++) {
        int gr = row0 + ty * 8 + r;
        float ps = 0.f, pd = 0.f;
        #pragma unroll
        for (int j = 0; j < 4; j++) {
            unsigned lo, hi;
            UNPACK2(lo, hi, acc[r][j]);
            float v0 = __uint_as_float(lo), v1 = __uint_as_float(hi);
            int c0 = tx + 16 * (2 * j), c1 = tx + 16 * (2 * j + 1);
            if (gr < NN) {
                if (c0 < COUT) {
                    Out[(size_t)gr * COUT + c0] = v0;
                    ps += v0 * asrc[c0];
                    pd += v0 * adst[c0];
                }
                if (c1 < COUT) {
                    Out[(size_t)gr * COUT + c1] = v1;
                    ps += v1 * asrc[c1];
                    pd += v1 * adst[c1];
                }
            }
        }
        #pragma unroll
        for (int o = 1; o < 16; o <<= 1) {
            ps += __shfl_xor_sync(0xffffffffu, ps, o);
            pd += __shfl_xor_sync(0xffffffffu, pd, o);
        }
        if (tx == 0 && gr < NN) { g_als[gr] = ps; g_ald[gr] = pd; }
    }
}

// ---------------- per-edge logits (coalesced eatt read) ---------------------
__global__ void k_alpha(const float* __restrict__ eatt, const int* __restrict__ src,
                        const int* __restrict__ dst, int cedoff) {
    int e = blockIdx.x * blockDim.x + threadIdx.x;
    if (e >= EE) return;
    const float4* er = (const float4*)(eatt + (size_t)e * 8);
    float4 e0 = er[0], e1 = er[1];
    const float* cd = g_ced + cedoff;
    float ae = e0.x * cd[0] + e0.y * cd[1] + e0.z * cd[2] + e0.w * cd[3]
             + e1.x * cd[4] + e1.y * cd[5] + e1.z * cd[6] + e1.w * cd[7];
    float a = g_als[src[e]] + g_ald[dst[e]] + ae;
    a = (a > 0.f) ? a : 0.2f * a;
    g_salpha[g_pos[e]] = a;
}

// ---------------- warp-per-node softmax + gather-agg (+BN stats) ------------
template <int C>
__launch_bounds__(256)
__global__ void k_agg(const float* __restrict__ bias, float* __restrict__ out,
                      int accoff) {
    __shared__ float s_sum[C];
    __shared__ float s_sq[C];
    const int tid = threadIdx.x;
    for (int c = tid; c < C; c += 256) { s_sum[c] = 0.f; s_sq[c] = 0.f; }
    __syncthreads();

    int gw = (blockIdx.x * 256 + tid) >> 5;
    int lane = tid & 31;
    constexpr int NV = C / 4;
    const bool act = lane < NV;

    if (gw < NN) {
        int beg = g_off[gw], end = g_off[gw + 1];

        float den = 0.f;
        for (int i = beg + lane; i < end; i += 32) den += __expf(g_salpha[i]);
        #pragma unroll
        for (int o = 16; o; o >>= 1) den += __shfl_xor_sync(0xffffffffu, den, o);
        float inv = (end > beg) ? 1.f / den : 0.f;

        float4 acc = make_float4(0.f, 0.f, 0.f, 0.f);
        int p = beg;
        for (; p + 2 <= end; p += 2) {
            float w0 = __expf(g_salpha[p]) * inv;
            float w1 = __expf(g_salpha[p + 1]) * inv;
            int s0 = g_ssrc[p], s1 = g_ssrc[p + 1];
            if (act) {
                float4 v0 = *(const float4*)(g_xs + (size_t)s0 * C + lane * 4);
                float4 v1 = *(const float4*)(g_xs + (size_t)s1 * C + lane * 4);
                acc.x += w0 * v0.x + w1 * v1.x;
                acc.y += w0 * v0.y + w1 * v1.y;
                acc.z += w0 * v0.z + w1 * v1.z;
                acc.w += w0 * v0.w + w1 * v1.w;
            }
        }
        if (p < end) {
            float w0 = __expf(g_salpha[p]) * inv;
            int s0 = g_ssrc[p];
            if (act) {
                float4 v0 = *(const float4*)(g_xs + (size_t)s0 * C + lane * 4);
                acc.x += w0 * v0.x; acc.y += w0 * v0.y;
                acc.z += w0 * v0.z; acc.w += w0 * v0.w;
            }
        }
        if (act) {
            float4 b = *(const float4*)(bias + lane * 4);
            acc.x += b.x; acc.y += b.y; acc.z += b.z; acc.w += b.w;
            *(float4*)(out + (size_t)gw * C + lane * 4) = acc;
            int c = lane * 4;
            atomicAdd(&s_sum[c + 0], acc.x); atomicAdd(&s_sq[c + 0], acc.x * acc.x);
            atomicAdd(&s_sum[c + 1], acc.y); atomicAdd(&s_sq[c + 1], acc.y * acc.y);
            atomicAdd(&s_sum[c + 2], acc.z); atomicAdd(&s_sq[c + 2], acc.z * acc.z);
            atomicAdd(&s_sum[c + 3], acc.w); atomicAdd(&s_sq[c + 3], acc.w * acc.w);
        }
    }
    __syncthreads();
    for (int c = tid; c < C; c += 256) {
        atomicAdd(&g_bnacc[accoff + c], s_sum[c]);
        atomicAdd(&g_bnacc[accoff + 128 + c], s_sq[c]);
    }
}

// ---------------- batchnorm finalize / final apply --------------------------
__global__ void k_bnfin(const float* __restrict__ g, const float* __restrict__ b,
                        int C, int accoff, int scoff) {
    int c = threadIdx.x;
    if (c < C) {
        float mean = g_bnacc[accoff + c] * (1.f / NN);
        float var = g_bnacc[accoff + 128 + c] * (1.f / NN) - mean * mean;
        float sc = g[c] * rsqrtf(var + 1e-5f);
        g_scale[scoff + c] = sc;
        g_shift[scoff + c] = b[c] - mean * sc;
    }
}

__global__ void k_out(const float* __restrict__ h, float* __restrict__ out) {
    int idx = blockIdx.x * blockDim.x + threadIdx.x;
    int i4 = idx * 4;
    if (i4 < NN * 112) {
        int c = i4 % 112;
        float4 v = *(const float4*)(h + i4);
        v.x = fmaf(v.x, g_scale[128 + c + 0], g_shift[128 + c + 0]);
        v.y = fmaf(v.y, g_scale[128 + c + 1], g_shift[128 + c + 1]);
        v.z = fmaf(v.z, g_scale[128 + c + 2], g_shift[128 + c + 2]);
        v.w = fmaf(v.w, g_scale[128 + c + 3], g_shift[128 + c + 3]);
        *(float4*)(out + i4) = v;
    }
}

// ---------------- launch -----------------------------------------------------
extern "C" void kernel_launch(void* const* d_in, const int* in_sizes, int n_in,
                              void* d_out, int out_size) {
    const float* x    = (const float*)d_in[0];
    const int*   ei   = (const int*)d_in[1];
    const float* eatt = (const float*)d_in[2];
    const float* W0   = (const float*)d_in[3];
    const float* as0  = (const float*)d_in[4];
    const float* ad0  = (const float*)d_in[5];
    const float* We0  = (const float*)d_in[6];
    const float* ae0  = (const float*)d_in[7];
    const float* b0   = (const float*)d_in[8];
    const float* W1   = (const float*)d_in[9];
    const float* as1  = (const float*)d_in[10];
    const float* ad1  = (const float*)d_in[11];
    const float* We1  = (const float*)d_in[12];
    const float* ae1  = (const float*)d_in[13];
    const float* b1   = (const float*)d_in[14];
    const float* bng  = (const float*)d_in[15];
    const float* bnb  = (const float*)d_in[16];
    const float* bfg  = (const float*)d_in[17];
    const float* bfb  = (const float*)d_in[18];
    float* out = (float*)d_out;

    const int* src = ei;
    const int* dst = ei + EE;

    float* p_xs = nullptr;
    float* p_h  = nullptr;
    cudaGetSymbolAddress((void**)&p_xs, g_xs);
    cudaGetSymbolAddress((void**)&p_h,  g_h);

    const int TB = 256;
    const int gE = (EE + TB - 1) / TB;
    const int gZ = (NN + TB - 1) / TB;
    const int gW = (NN * 32 + TB - 1) / TB;
    const int gG = (NN + 127) / 128;

    // CSR build
    k_zero<<<gZ, TB>>>();
    k_hist<<<gE, TB>>>(dst);
    k_scan_part<<<NBLK, 1024>>>();
    k_scan_top<<<1, 32>>>();
    k_scan_apply<<<NBLK, 1024>>>();
    k_scatter<<<gE, TB>>>(src, dst);
    k_ced<<<1, 32>>>(We0, ae0, We1, ae1);

    // layer 0
    k_gemm<128, false><<<gG, 256>>>(x, W0, as0, ad0, p_xs);
    k_alpha<<<gE, TB>>>(eatt, src, dst, 0);
    k_agg<128><<<gW, TB>>>(b0, p_h, 0);
    k_bnfin<<<1, 128>>>(bng, bnb, 128, 0, 0);

    // layer 1 (BN+relu fused into A-load)
    k_gemm<112, true><<<gG, 256>>>(p_h, W1, as1, ad1, p_xs);
    k_alpha<<<gE, TB>>>(eatt, src, dst, 8);
    k_agg<112><<<gW, TB>>>(b1, p_h, 256);
    k_bnfin<<<1, 128>>>(bfg, bfb, 112, 256, 128);
    k_out<<<(NN * 112 / 4 + TB - 1) / TB, TB>>>(p_h, out);
}

// round 3
// speedup vs baseline: 1.2417x; 1.0643x over previous
#include <cuda_runtime.h>
#include <cstdint>

#define NN 50000
#define EE 800000
#define NBLK 49   // ceil(50000/1024)

// ---------------- scratch (device globals) ----------------------------------
__device__ __align__(16) float g_xs[NN * 128];
__device__ __align__(16) float g_h[NN * 128];
__device__ float g_als[NN];
__device__ float g_ald[NN];
__device__ float g_salpha[EE];   // exp(leaky(alpha0)), sorted order
__device__ float g_ae1s[EE];     // layer-1 edge term, sorted order
__device__ int   g_deg[NN];
__device__ int   g_off[NN + 1];
__device__ int   g_cur[NN];
__device__ int   g_ssrc[EE];
__device__ int   g_pos[EE];
__device__ int   g_bsum[64];
__device__ int   g_boff[64];
__device__ float g_bnacc[512];   // [sum0|sq0|sum1|sq1] x128
__device__ float g_scale[256];
__device__ float g_shift[256];
__device__ float g_ced[16];      // [0:8) layer0, [8:16) layer1

// ---------------- f32x2 packed math (sm_100+) ------------------------------
#define FMA2(d, a, b, c) \
    asm("fma.rn.f32x2 %0, %1, %2, %3;" : "=l"(d) : "l"(a), "l"(b), "l"(c))
#define PACK2(d, lo, hi) \
    asm("mov.b64 %0, {%1, %2};" : "=l"(d) : "r"(lo), "r"(hi))
#define UNPACK2(lo, hi, s) \
    asm("mov.b64 {%0, %1}, %2;" : "=r"(lo), "=r"(hi) : "l"(s))

// ---------------- init + CSR build ------------------------------------------
__global__ void k_zero() {
    int i = blockIdx.x * blockDim.x + threadIdx.x;
    if (i < NN) g_deg[i] = 0;
    if (i < 512) g_bnacc[i] = 0.f;
}

__global__ void k_hist(const int* __restrict__ dst) {
    int e = blockIdx.x * blockDim.x + threadIdx.x;
    if (e < EE) atomicAdd(&g_deg[dst[e]], 1);
}

__global__ __launch_bounds__(1024) void k_scan_part() {
    __shared__ int ws[32];
    const int tid = threadIdx.x, lane = tid & 31, wid = tid >> 5;
    int i = blockIdx.x * 1024 + tid;
    int v = (i < NN) ? g_deg[i] : 0;
    int x = v;
    #pragma unroll
    for (int o = 1; o < 32; o <<= 1) {
        int t = __shfl_up_sync(0xffffffffu, x, o);
        if (lane >= o) x += t;
    }
    if (lane == 31) ws[wid] = x;
    __syncthreads();
    if (wid == 0) {
        int y = ws[lane];
        #pragma unroll
        for (int o = 1; o < 32; o <<= 1) {
            int t = __shfl_up_sync(0xffffffffu, y, o);
            if (lane >= o) y += t;
        }
        ws[lane] = y;
    }
    __syncthreads();
    int excl = x - v + ((wid > 0) ? ws[wid - 1] : 0);
    if (i < NN) g_off[i] = excl;
    if (tid == 1023) g_bsum[blockIdx.x] = excl + v;
}

__global__ void k_scan_top() {
    __shared__ int w0tot;
    int t = threadIdx.x;          // 64 threads
    int lane = t & 31, wid = t >> 5;
    int v = (t < NBLK) ? g_bsum[t] : 0;
    int x = v;
    #pragma unroll
    for (int o = 1; o < 32; o <<= 1) {
        int u = __shfl_up_sync(0xffffffffu, x, o);
        if (lane >= o) x += u;
    }
    if (wid == 0 && lane == 31) w0tot = x;
    __syncthreads();
    int incl = x + ((wid == 1) ? w0tot : 0);
    if (t < NBLK) g_boff[t] = incl - v;
    if (t == NBLK - 1) g_off[NN] = incl;
}

__global__ __launch_bounds__(1024) void k_scan_apply() {
    int i = blockIdx.x * 1024 + threadIdx.x;
    if (i < NN) {
        int o = g_off[i] + g_boff[blockIdx.x];
        g_off[i] = o;
        g_cur[i] = o;
    }
}

__global__ void k_scatter(const int* __restrict__ src, const int* __restrict__ dst) {
    int e = blockIdx.x * blockDim.x + threadIdx.x;
    if (e >= EE) return;
    int p = atomicAdd(&g_cur[dst[e]], 1);
    g_ssrc[p] = src[e];
    g_pos[e] = p;
}

// ---------------- ced for both layers ---------------------------------------
__global__ void k_ced(const float* __restrict__ We0, const float* __restrict__ ae0,
                      const float* __restrict__ We1, const float* __restrict__ ae1) {
    int j = threadIdx.x;
    if (j < 8) {
        float s = 0.f;
        for (int c = 0; c < 128; c++) s += We0[j * 128 + c] * ae0[c];
        g_ced[j] = s;
    } else if (j < 16) {
        int jj = j - 8;
        float s = 0.f;
        for (int c = 0; c < 112; c++) s += We1[jj * 112 + c] * ae1[c];
        g_ced[j] = s;
    }
}

// ---------------- GEMM (+optional BN-relu pre, +al epilogue) ----------------
template <int COUT, bool PRE>
__launch_bounds__(256)
__global__ void k_gemm(const float* __restrict__ A, const float* __restrict__ W,
                       const float* __restrict__ asrc, const float* __restrict__ adst,
                       float* __restrict__ Out) {
    __shared__ float As[128 * 33];
    __shared__ float Bs[32 * 128];
    const int tid = threadIdx.x;
    const int tx = tid & 15, ty = tid >> 4;
    const int row0 = blockIdx.x * 128;

    unsigned long long acc[8][4];
    #pragma unroll
    for (int r = 0; r < 8; r++)
        #pragma unroll
        for (int j = 0; j < 4; j++) acc[r][j] = 0ull;

    for (int k0 = 0; k0 < 128; k0 += 32) {
        #pragma unroll
        for (int t = 0; t < 4; t++) {
            int idx = tid + t * 256;
            int r = idx >> 3, c4 = (idx & 7) * 4;
            int gr = row0 + r;
            float4 v = make_float4(0.f, 0.f, 0.f, 0.f);
            if (gr < NN) {
                v = *(const float4*)(A + (size_t)gr * 128 + k0 + c4);
                if (PRE) {
                    int ch = k0 + c4;
                    v.x = fmaxf(fmaf(v.x, g_scale[ch + 0], g_shift[ch + 0]), 0.f);
                    v.y = fmaxf(fmaf(v.y, g_scale[ch + 1], g_shift[ch + 1]), 0.f);
                    v.z = fmaxf(fmaf(v.z, g_scale[ch + 2], g_shift[ch + 2]), 0.f);
                    v.w = fmaxf(fmaf(v.w, g_scale[ch + 3], g_shift[ch + 3]), 0.f);
                }
            }
            float* dp = &As[r * 33 + c4];
            dp[0] = v.x; dp[1] = v.y; dp[2] = v.z; dp[3] = v.w;
        }
        #pragma unroll
        for (int t = 0; t < 16; t++) {
            int idx = tid + t * 256;
            int kk = idx >> 7, c = idx & 127;
            Bs[idx] = (c < COUT) ? W[(size_t)(k0 + kk) * COUT + c] : 0.f;
        }
        __syncthreads();
        #pragma unroll
        for (int kk = 0; kk < 32; kk++) {
            float a[8], b[8];
            #pragma unroll
            for (int r = 0; r < 8; r++) a[r] = As[(ty * 8 + r) * 33 + kk];
            #pragma unroll
            for (int j = 0; j < 8; j++) b[j] = Bs[kk * 128 + tx + 16 * j];
            unsigned long long b2[4];
            #pragma unroll
            for (int j = 0; j < 4; j++)
                PACK2(b2[j], __float_as_uint(b[2 * j]), __float_as_uint(b[2 * j + 1]));
            #pragma unroll
            for (int r = 0; r < 8; r++) {
                unsigned long long a2;
                PACK2(a2, __float_as_uint(a[r]), __float_as_uint(a[r]));
                #pragma unroll
                for (int j = 0; j < 4; j++) FMA2(acc[r][j], a2, b2[j], acc[r][j]);
            }
        }
        __syncthreads();
    }
    #pragma unroll
    for (int r = 0; r < 8; r++) {
        int gr = row0 + ty * 8 + r;
        float ps = 0.f, pd = 0.f;
        #pragma unroll
        for (int j = 0; j < 4; j++) {
            unsigned lo, hi;
            UNPACK2(lo, hi, acc[r][j]);
            float v0 = __uint_as_float(lo), v1 = __uint_as_float(hi);
            int c0 = tx + 16 * (2 * j), c1 = tx + 16 * (2 * j + 1);
            if (gr < NN) {
                if (c0 < COUT) {
                    Out[(size_t)gr * COUT + c0] = v0;
                    ps += v0 * asrc[c0];
                    pd += v0 * adst[c0];
                }
                if (c1 < COUT) {
                    Out[(size_t)gr * COUT + c1] = v1;
                    ps += v1 * asrc[c1];
                    pd += v1 * adst[c1];
                }
            }
        }
        #pragma unroll
        for (int o = 1; o < 16; o <<= 1) {
            ps += __shfl_xor_sync(0xffffffffu, ps, o);
            pd += __shfl_xor_sync(0xffffffffu, pd, o);
        }
        if (tx == 0 && gr < NN) { g_als[gr] = ps; g_ald[gr] = pd; }
    }
}

// ---------------- fused per-edge logits: one eatt pass for BOTH layers ------
__global__ void k_alphaF(const float* __restrict__ eatt, const int* __restrict__ src,
                         const int* __restrict__ dst) {
    int e = blockIdx.x * blockDim.x + threadIdx.x;
    if (e >= EE) return;
    const float4* er = (const float4*)(eatt + (size_t)e * 8);
    float4 e0 = er[0], e1 = er[1];
    float ae0 = e0.x * g_ced[0] + e0.y * g_ced[1] + e0.z * g_ced[2] + e0.w * g_ced[3]
              + e1.x * g_ced[4] + e1.y * g_ced[5] + e1.z * g_ced[6] + e1.w * g_ced[7];
    float ae1 = e0.x * g_ced[8] + e0.y * g_ced[9] + e0.z * g_ced[10] + e0.w * g_ced[11]
              + e1.x * g_ced[12] + e1.y * g_ced[13] + e1.z * g_ced[14] + e1.w * g_ced[15];
    float a = g_als[src[e]] + g_ald[dst[e]] + ae0;
    a = (a > 0.f) ? a : 0.2f * a;
    int p = g_pos[e];
    g_salpha[p] = __expf(a);
    g_ae1s[p] = ae1;
}

// ------- warp-per-node single-pass agg (+BN stats). ALPHA1: inline logits ---
template <int C, bool ALPHA1>
__launch_bounds__(256)
__global__ void k_agg(const float* __restrict__ bias, float* __restrict__ out,
                      int accoff) {
    __shared__ float s_sum[C];
    __shared__ float s_sq[C];
    const int tid = threadIdx.x;
    for (int c = tid; c < C; c += 256) { s_sum[c] = 0.f; s_sq[c] = 0.f; }
    __syncthreads();

    int gw = (blockIdx.x * 256 + tid) >> 5;
    int lane = tid & 31;
    constexpr int NV = C / 4;
    const bool act = lane < NV;

    if (gw < NN) {
        int beg = g_off[gw], end = g_off[gw + 1];
        float aldv = ALPHA1 ? g_ald[gw] : 0.f;

        float den = 0.f;
        float4 acc = make_float4(0.f, 0.f, 0.f, 0.f);
        int p = beg;
        for (; p + 2 <= end; p += 2) {
            int s0 = g_ssrc[p], s1 = g_ssrc[p + 1];
            float w0, w1;
            if (ALPHA1) {
                float a0 = g_als[s0] + aldv + g_ae1s[p];
                float a1 = g_als[s1] + aldv + g_ae1s[p + 1];
                a0 = (a0 > 0.f) ? a0 : 0.2f * a0;
                a1 = (a1 > 0.f) ? a1 : 0.2f * a1;
                w0 = __expf(a0); w1 = __expf(a1);
            } else {
                w0 = g_salpha[p]; w1 = g_salpha[p + 1];
            }
            den += w0 + w1;
            if (act) {
                float4 v0 = *(const float4*)(g_xs + (size_t)s0 * C + lane * 4);
                float4 v1 = *(const float4*)(g_xs + (size_t)s1 * C + lane * 4);
                acc.x += w0 * v0.x + w1 * v1.x;
                acc.y += w0 * v0.y + w1 * v1.y;
                acc.z += w0 * v0.z + w1 * v1.z;
                acc.w += w0 * v0.w + w1 * v1.w;
            }
        }
        if (p < end) {
            int s0 = g_ssrc[p];
            float w0;
            if (ALPHA1) {
                float a0 = g_als[s0] + aldv + g_ae1s[p];
                a0 = (a0 > 0.f) ? a0 : 0.2f * a0;
                w0 = __expf(a0);
            } else {
                w0 = g_salpha[p];
            }
            den += w0;
            if (act) {
                float4 v0 = *(const float4*)(g_xs + (size_t)s0 * C + lane * 4);
                acc.x += w0 * v0.x; acc.y += w0 * v0.y;
                acc.z += w0 * v0.z; acc.w += w0 * v0.w;
            }
        }
        float inv = (end > beg) ? 1.f / den : 0.f;
        if (act) {
            float4 b = *(const float4*)(bias + lane * 4);
            acc.x = fmaf(acc.x, inv, b.x);
            acc.y = fmaf(acc.y, inv, b.y);
            acc.z = fmaf(acc.z, inv, b.z);
            acc.w = fmaf(acc.w, inv, b.w);
            *(float4*)(out + (size_t)gw * C + lane * 4) = acc;
            int c = lane * 4;
            atomicAdd(&s_sum[c + 0], acc.x); atomicAdd(&s_sq[c + 0], acc.x * acc.x);
            atomicAdd(&s_sum[c + 1], acc.y); atomicAdd(&s_sq[c + 1], acc.y * acc.y);
            atomicAdd(&s_sum[c + 2], acc.z); atomicAdd(&s_sq[c + 2], acc.z * acc.z);
            atomicAdd(&s_sum[c + 3], acc.w); atomicAdd(&s_sq[c + 3], acc.w * acc.w);
        }
    }
    __syncthreads();
    for (int c = tid; c < C; c += 256) {
        atomicAdd(&g_bnacc[accoff + c], s_sum[c]);
        atomicAdd(&g_bnacc[accoff + 128 + c], s_sq[c]);
    }
}

// ---------------- batchnorm finalize / final apply --------------------------
__global__ void k_bnfin(const float* __restrict__ g, const float* __restrict__ b,
                        int C, int accoff, int scoff) {
    int c = threadIdx.x;
    if (c < C) {
        float mean = g_bnacc[accoff + c] * (1.f / NN);
        float var = g_bnacc[accoff + 128 + c] * (1.f / NN) - mean * mean;
        float sc = g[c] * rsqrtf(var + 1e-5f);
        g_scale[scoff + c] = sc;
        g_shift[scoff + c] = b[c] - mean * sc;
    }
}

__global__ void k_out(const float* __restrict__ h, float* __restrict__ out) {
    int idx = blockIdx.x * blockDim.x + threadIdx.x;
    int i4 = idx * 4;
    if (i4 < NN * 112) {
        int c = i4 % 112;
        float4 v = *(const float4*)(h + i4);
        v.x = fmaf(v.x, g_scale[128 + c + 0], g_shift[128 + c + 0]);
        v.y = fmaf(v.y, g_scale[128 + c + 1], g_shift[128 + c + 1]);
        v.z = fmaf(v.z, g_scale[128 + c + 2], g_shift[128 + c + 2]);
        v.w = fmaf(v.w, g_scale[128 + c + 3], g_shift[128 + c + 3]);
        *(float4*)(out + i4) = v;
    }
}

// ---------------- launch -----------------------------------------------------
extern "C" void kernel_launch(void* const* d_in, const int* in_sizes, int n_in,
                              void* d_out, int out_size) {
    const float* x    = (const float*)d_in[0];
    const int*   ei   = (const int*)d_in[1];
    const float* eatt = (const float*)d_in[2];
    const float* W0   = (const float*)d_in[3];
    const float* as0  = (const float*)d_in[4];
    const float* ad0  = (const float*)d_in[5];
    const float* We0  = (const float*)d_in[6];
    const float* ae0  = (const float*)d_in[7];
    const float* b0   = (const float*)d_in[8];
    const float* W1   = (const float*)d_in[9];
    const float* as1  = (const float*)d_in[10];
    const float* ad1  = (const float*)d_in[11];
    const float* We1  = (const float*)d_in[12];
    const float* ae1  = (const float*)d_in[13];
    const float* b1   = (const float*)d_in[14];
    const float* bng  = (const float*)d_in[15];
    const float* bnb  = (const float*)d_in[16];
    const float* bfg  = (const float*)d_in[17];
    const float* bfb  = (const float*)d_in[18];
    float* out = (float*)d_out;

    const int* src = ei;
    const int* dst = ei + EE;

    float* p_xs = nullptr;
    float* p_h  = nullptr;
    cudaGetSymbolAddress((void**)&p_xs, g_xs);
    cudaGetSymbolAddress((void**)&p_h,  g_h);

    // fork-join resources (host-side only; created once)
    static cudaStream_t s1 = nullptr;
    static cudaEvent_t evFork = nullptr, evJoin = nullptr;
    if (!s1) {
        cudaStreamCreateWithFlags(&s1, cudaStreamNonBlocking);
        cudaEventCreateWithFlags(&evFork, cudaEventDisableTiming);
        cudaEventCreateWithFlags(&evJoin, cudaEventDisableTiming);
    }

    const int TB = 256;
    const int gE = (EE + TB - 1) / TB;
    const int gZ = (NN + TB - 1) / TB;
    const int gW = (NN * 32 + TB - 1) / TB;
    const int gG = (NN + 127) / 128;

    // ---- fork: CSR build on s1, concurrent with ced+gemm0 on main stream
    cudaEventRecord(evFork, 0);
    cudaStreamWaitEvent(s1, evFork, 0);

    k_zero<<<gZ, TB, 0, s1>>>();
    k_hist<<<gE, TB, 0, s1>>>(dst);
    k_scan_part<<<NBLK, 1024, 0, s1>>>();
    k_scan_top<<<1, 64, 0, s1>>>();
    k_scan_apply<<<NBLK, 1024, 0, s1>>>();
    k_scatter<<<gE, TB, 0, s1>>>(src, dst);
    cudaEventRecord(evJoin, s1);

    k_ced<<<1, 32>>>(We0, ae0, We1, ae1);
    k_gemm<128, false><<<gG, 256>>>(x, W0, as0, ad0, p_xs);

    cudaStreamWaitEvent(0, evJoin, 0);

    // ---- layer 0
    k_alphaF<<<gE, TB>>>(eatt, src, dst);
    k_agg<128, false><<<gW, TB>>>(b0, p_h, 0);
    k_bnfin<<<1, 128>>>(bng, bnb, 128, 0, 0);

    // ---- layer 1 (BN+relu fused into A-load; alpha computed inline in agg)
    k_gemm<112, true><<<gG, 256>>>(p_h, W1, as1, ad1, p_xs);
    k_agg<112, true><<<gW, TB>>>(b1, p_h, 256);
    k_bnfin<<<1, 128>>>(bfg, bfb, 112, 256, 128);
    k_out<<<(NN * 112 / 4 + TB - 1) / TB, TB>>>(p_h, out);
}

// round 4
// speedup vs baseline: 1.3098x; 1.0549x over previous
#include <cuda_runtime.h>
#include <cstdint>

#define NN 50000
#define EE 800000
#define NBLK 49   // ceil(50000/1024)

// ---------------- scratch (device globals; zero-init at load) ---------------
__device__ __align__(16) float g_xs[NN * 128];
__device__ __align__(16) float g_h[NN * 128];
__device__ float g_als[NN];
__device__ float g_ald[NN];
__device__ float g_salpha[EE];   // exp(leaky(alpha0)), sorted order
__device__ float g_ae1s[EE];     // layer-1 edge term, sorted order
__device__ int   g_deg[NN];      // self-cleaned in k_scan_apply
__device__ int   g_off[NN + 1];
__device__ int   g_cur[NN];
__device__ int   g_ssrc[EE];
__device__ int   g_pos[EE];
__device__ int   g_bsum[64];
__device__ float g_bnacc[512];   // self-cleaned in agg finalizer
__device__ unsigned g_ctr[2];    // self-cleaned in agg finalizer
__device__ float g_scale[256];
__device__ float g_shift[256];
__device__ float g_ced[16];

// ---------------- f32x2 packed math (sm_100+) ------------------------------
#define FMA2(d, a, b, c) \
    asm("fma.rn.f32x2 %0, %1, %2, %3;" : "=l"(d) : "l"(a), "l"(b), "l"(c))
#define PACK2(d, lo, hi) \
    asm("mov.b64 %0, {%1, %2};" : "=l"(d) : "r"(lo), "r"(hi))
#define UNPACK2(lo, hi, s) \
    asm("mov.b64 {%0, %1}, %2;" : "=r"(lo), "=r"(hi) : "l"(s))

// ---------------- CSR build -------------------------------------------------
__global__ void k_hist(const int* __restrict__ dst) {
    int e = blockIdx.x * blockDim.x + threadIdx.x;
    if (e < EE) atomicAdd(&g_deg[dst[e]], 1);
}

__global__ __launch_bounds__(1024) void k_scan_part() {
    __shared__ int ws[32];
    const int tid = threadIdx.x, lane = tid & 31, wid = tid >> 5;
    int i = blockIdx.x * 1024 + tid;
    int v = (i < NN) ? g_deg[i] : 0;
    int x = v;
    #pragma unroll
    for (int o = 1; o < 32; o <<= 1) {
        int t = __shfl_up_sync(0xffffffffu, x, o);
        if (lane >= o) x += t;
    }
    if (lane == 31) ws[wid] = x;
    __syncthreads();
    if (wid == 0) {
        int y = ws[lane];
        #pragma unroll
        for (int o = 1; o < 32; o <<= 1) {
            int t = __shfl_up_sync(0xffffffffu, y, o);
            if (lane >= o) y += t;
        }
        ws[lane] = y;
    }
    __syncthreads();
    int excl = x - v + ((wid > 0) ? ws[wid - 1] : 0);
    if (i < NN) g_off[i] = excl;
    if (tid == 1023) g_bsum[blockIdx.x] = excl + v;
}

// scan_apply with inline block-prefix over g_bsum; also zeroes g_deg
__global__ __launch_bounds__(1024) void k_scan_apply() {
    __shared__ int s_pre[2];
    const int tid = threadIdx.x, bid = blockIdx.x;
    if (tid < 64) {
        int v = (tid < bid) ? g_bsum[tid] : 0;
        #pragma unroll
        for (int o = 16; o; o >>= 1) v += __shfl_xor_sync(0xffffffffu, v, o);
        if ((tid & 31) == 0) s_pre[tid >> 5] = v;
    }
    __syncthreads();
    int bp = s_pre[0] + s_pre[1];
    int i = bid * 1024 + tid;
    if (i < NN) {
        int o = g_off[i] + bp;
        g_off[i] = o;
        g_cur[i] = o;
        g_deg[i] = 0;    // self-clean for next invocation
    }
    if (bid == NBLK - 1 && tid == 1023) g_off[NN] = bp + g_bsum[NBLK - 1];
}

__global__ void k_scatter(const int* __restrict__ src, const int* __restrict__ dst) {
    int e = blockIdx.x * blockDim.x + threadIdx.x;
    if (e >= EE) return;
    int p = atomicAdd(&g_cur[dst[e]], 1);
    g_ssrc[p] = src[e];
    g_pos[e] = p;
}

// ---------------- ced for both layers ---------------------------------------
__global__ void k_ced(const float* __restrict__ We0, const float* __restrict__ ae0,
                      const float* __restrict__ We1, const float* __restrict__ ae1) {
    int j = threadIdx.x;
    if (j < 8) {
        float s = 0.f;
        for (int c = 0; c < 128; c++) s += We0[j * 128 + c] * ae0[c];
        g_ced[j] = s;
    } else if (j < 16) {
        int jj = j - 8;
        float s = 0.f;
        for (int c = 0; c < 112; c++) s += We1[jj * 112 + c] * ae1[c];
        g_ced[j] = s;
    }
}

// ---------------- GEMM (+optional BN-relu pre, +al epilogue) ----------------
template <int COUT, bool PRE>
__launch_bounds__(256)
__global__ void k_gemm(const float* __restrict__ A, const float* __restrict__ W,
                       const float* __restrict__ asrc, const float* __restrict__ adst,
                       float* __restrict__ Out) {
    __shared__ float As[128 * 33];
    __shared__ float Bs[32 * 128];
    const int tid = threadIdx.x;
    const int tx = tid & 15, ty = tid >> 4;
    const int row0 = blockIdx.x * 128;

    unsigned long long acc[8][4];
    #pragma unroll
    for (int r = 0; r < 8; r++)
        #pragma unroll
        for (int j = 0; j < 4; j++) acc[r][j] = 0ull;

    for (int k0 = 0; k0 < 128; k0 += 32) {
        #pragma unroll
        for (int t = 0; t < 4; t++) {
            int idx = tid + t * 256;
            int r = idx >> 3, c4 = (idx & 7) * 4;
            int gr = row0 + r;
            float4 v = make_float4(0.f, 0.f, 0.f, 0.f);
            if (gr < NN) {
                v = *(const float4*)(A + (size_t)gr * 128 + k0 + c4);
                if (PRE) {
                    int ch = k0 + c4;
                    v.x = fmaxf(fmaf(v.x, g_scale[ch + 0], g_shift[ch + 0]), 0.f);
                    v.y = fmaxf(fmaf(v.y, g_scale[ch + 1], g_shift[ch + 1]), 0.f);
                    v.z = fmaxf(fmaf(v.z, g_scale[ch + 2], g_shift[ch + 2]), 0.f);
                    v.w = fmaxf(fmaf(v.w, g_scale[ch + 3], g_shift[ch + 3]), 0.f);
                }
            }
            float* dp = &As[r * 33 + c4];
            dp[0] = v.x; dp[1] = v.y; dp[2] = v.z; dp[3] = v.w;
        }
        #pragma unroll
        for (int t = 0; t < 16; t++) {
            int idx = tid + t * 256;
            int kk = idx >> 7, c = idx & 127;
            Bs[idx] = (c < COUT) ? W[(size_t)(k0 + kk) * COUT + c] : 0.f;
        }
        __syncthreads();
        #pragma unroll
        for (int kk = 0; kk < 32; kk++) {
            float a[8], b[8];
            #pragma unroll
            for (int r = 0; r < 8; r++) a[r] = As[(ty * 8 + r) * 33 + kk];
            #pragma unroll
            for (int j = 0; j < 8; j++) b[j] = Bs[kk * 128 + tx + 16 * j];
            unsigned long long b2[4];
            #pragma unroll
            for (int j = 0; j < 4; j++)
                PACK2(b2[j], __float_as_uint(b[2 * j]), __float_as_uint(b[2 * j + 1]));
            #pragma unroll
            for (int r = 0; r < 8; r++) {
                unsigned long long a2;
                PACK2(a2, __float_as_uint(a[r]), __float_as_uint(a[r]));
                #pragma unroll
                for (int j = 0; j < 4; j++) FMA2(acc[r][j], a2, b2[j], acc[r][j]);
            }
        }
        __syncthreads();
    }
    #pragma unroll
    for (int r = 0; r < 8; r++) {
        int gr = row0 + ty * 8 + r;
        float ps = 0.f, pd = 0.f;
        #pragma unroll
        for (int j = 0; j < 4; j++) {
            unsigned lo, hi;
            UNPACK2(lo, hi, acc[r][j]);
            float v0 = __uint_as_float(lo), v1 = __uint_as_float(hi);
            int c0 = tx + 16 * (2 * j), c1 = tx + 16 * (2 * j + 1);
            if (gr < NN) {
                if (c0 < COUT) {
                    Out[(size_t)gr * COUT + c0] = v0;
                    ps += v0 * asrc[c0];
                    pd += v0 * adst[c0];
                }
                if (c1 < COUT) {
                    Out[(size_t)gr * COUT + c1] = v1;
                    ps += v1 * asrc[c1];
                    pd += v1 * adst[c1];
                }
            }
        }
        #pragma unroll
        for (int o = 1; o < 16; o <<= 1) {
            ps += __shfl_xor_sync(0xffffffffu, ps, o);
            pd += __shfl_xor_sync(0xffffffffu, pd, o);
        }
        if (tx == 0 && gr < NN) { g_als[gr] = ps; g_ald[gr] = pd; }
    }
}

// ---------------- fused per-edge logits: one eatt pass for BOTH layers ------
__global__ void k_alphaF(const float* __restrict__ eatt, const int* __restrict__ src,
                         const int* __restrict__ dst) {
    int e = blockIdx.x * blockDim.x + threadIdx.x;
    if (e >= EE) return;
    const float4* er = (const float4*)(eatt + (size_t)e * 8);
    float4 e0 = er[0], e1 = er[1];
    float ae0 = e0.x * g_ced[0] + e0.y * g_ced[1] + e0.z * g_ced[2] + e0.w * g_ced[3]
              + e1.x * g_ced[4] + e1.y * g_ced[5] + e1.z * g_ced[6] + e1.w * g_ced[7];
    float ae1 = e0.x * g_ced[8] + e0.y * g_ced[9] + e0.z * g_ced[10] + e0.w * g_ced[11]
              + e1.x * g_ced[12] + e1.y * g_ced[13] + e1.z * g_ced[14] + e1.w * g_ced[15];
    float a = g_als[src[e]] + g_ald[dst[e]] + ae0;
    a = (a > 0.f) ? a : 0.2f * a;
    int p = g_pos[e];
    g_salpha[p] = __expf(a);
    g_ae1s[p] = ae1;
}

// ------- warp-per-node single-pass agg + fused BN stat/finalize -------------
template <int C, bool ALPHA1>
__launch_bounds__(256)
__global__ void k_agg(const float* __restrict__ bias, float* __restrict__ out,
                      const float* __restrict__ bgam, const float* __restrict__ bbet,
                      int accoff, int scoff, int cidx) {
    __shared__ float s_sum[C];
    __shared__ float s_sq[C];
    __shared__ unsigned s_ticket;
    const int tid = threadIdx.x;
    for (int c = tid; c < C; c += 256) { s_sum[c] = 0.f; s_sq[c] = 0.f; }
    __syncthreads();

    int gw = (blockIdx.x * 256 + tid) >> 5;
    int lane = tid & 31;
    constexpr int NV = C / 4;
    const bool act = lane < NV;

    if (gw < NN) {
        int beg = g_off[gw], end = g_off[gw + 1];
        float aldv = ALPHA1 ? g_ald[gw] : 0.f;

        float den = 0.f;
        float4 acc = make_float4(0.f, 0.f, 0.f, 0.f);
        int p = beg;
        for (; p + 4 <= end; p += 4) {
            int s0 = g_ssrc[p], s1 = g_ssrc[p + 1];
            int s2 = g_ssrc[p + 2], s3 = g_ssrc[p + 3];
            float w0, w1, w2, w3;
            if (ALPHA1) {
                float a0 = g_als[s0] + aldv + g_ae1s[p];
                float a1 = g_als[s1] + aldv + g_ae1s[p + 1];
                float a2 = g_als[s2] + aldv + g_ae1s[p + 2];
                float a3 = g_als[s3] + aldv + g_ae1s[p + 3];
                a0 = (a0 > 0.f) ? a0 : 0.2f * a0;
                a1 = (a1 > 0.f) ? a1 : 0.2f * a1;
                a2 = (a2 > 0.f) ? a2 : 0.2f * a2;
                a3 = (a3 > 0.f) ? a3 : 0.2f * a3;
                w0 = __expf(a0); w1 = __expf(a1); w2 = __expf(a2); w3 = __expf(a3);
            } else {
                w0 = g_salpha[p]; w1 = g_salpha[p + 1];
                w2 = g_salpha[p + 2]; w3 = g_salpha[p + 3];
            }
            den += (w0 + w1) + (w2 + w3);
            if (act) {
                float4 v0 = *(const float4*)(g_xs + (size_t)s0 * C + lane * 4);
                float4 v1 = *(const float4*)(g_xs + (size_t)s1 * C + lane * 4);
                float4 v2 = *(const float4*)(g_xs + (size_t)s2 * C + lane * 4);
                float4 v3 = *(const float4*)(g_xs + (size_t)s3 * C + lane * 4);
                acc.x += (w0 * v0.x + w1 * v1.x) + (w2 * v2.x + w3 * v3.x);
                acc.y += (w0 * v0.y + w1 * v1.y) + (w2 * v2.y + w3 * v3.y);
                acc.z += (w0 * v0.z + w1 * v1.z) + (w2 * v2.z + w3 * v3.z);
                acc.w += (w0 * v0.w + w1 * v1.w) + (w2 * v2.w + w3 * v3.w);
            }
        }
        for (; p < end; p++) {
            int s0 = g_ssrc[p];
            float w0;
            if (ALPHA1) {
                float a0 = g_als[s0] + aldv + g_ae1s[p];
                a0 = (a0 > 0.f) ? a0 : 0.2f * a0;
                w0 = __expf(a0);
            } else {
                w0 = g_salpha[p];
            }
            den += w0;
            if (act) {
                float4 v0 = *(const float4*)(g_xs + (size_t)s0 * C + lane * 4);
                acc.x += w0 * v0.x; acc.y += w0 * v0.y;
                acc.z += w0 * v0.z; acc.w += w0 * v0.w;
            }
        }
        float inv = (end > beg) ? 1.f / den : 0.f;
        if (act) {
            float4 b = *(const float4*)(bias + lane * 4);
            acc.x = fmaf(acc.x, inv, b.x);
            acc.y = fmaf(acc.y, inv, b.y);
            acc.z = fmaf(acc.z, inv, b.z);
            acc.w = fmaf(acc.w, inv, b.w);
            *(float4*)(out + (size_t)gw * C + lane * 4) = acc;
            int c = lane * 4;
            atomicAdd(&s_sum[c + 0], acc.x); atomicAdd(&s_sq[c + 0], acc.x * acc.x);
            atomicAdd(&s_sum[c + 1], acc.y); atomicAdd(&s_sq[c + 1], acc.y * acc.y);
            atomicAdd(&s_sum[c + 2], acc.z); atomicAdd(&s_sq[c + 2], acc.z * acc.z);
            atomicAdd(&s_sum[c + 3], acc.w); atomicAdd(&s_sq[c + 3], acc.w * acc.w);
        }
    }
    __syncthreads();
    for (int c = tid; c < C; c += 256) {
        atomicAdd(&g_bnacc[accoff + c], s_sum[c]);
        atomicAdd(&g_bnacc[accoff + 128 + c], s_sq[c]);
    }
    // last-block BN finalize (threadfence + ticket)
    __threadfence();
    __syncthreads();
    if (tid == 0) s_ticket = atomicAdd(&g_ctr[cidx], 1u);
    __syncthreads();
    if (s_ticket == gridDim.x - 1) {
        __threadfence();
        if (tid < C) {
            float sum = __ldcg(&g_bnacc[accoff + tid]);
            float sq  = __ldcg(&g_bnacc[accoff + 128 + tid]);
            float mean = sum * (1.f / NN);
            float var = sq * (1.f / NN) - mean * mean;
            float sc = bgam[tid] * rsqrtf(var + 1e-5f);
            g_scale[scoff + tid] = sc;
            g_shift[scoff + tid] = bbet[tid] - mean * sc;
            g_bnacc[accoff + tid] = 0.f;          // self-clean
            g_bnacc[accoff + 128 + tid] = 0.f;
        }
        if (tid == 0) g_ctr[cidx] = 0u;           // self-clean
    }
}

// ---------------- final BN apply ---------------------------------------------
__global__ void k_out(const float* __restrict__ h, float* __restrict__ out) {
    int idx = blockIdx.x * blockDim.x + threadIdx.x;
    int i4 = idx * 4;
    if (i4 < NN * 112) {
        int c = i4 % 112;
        float4 v = *(const float4*)(h + i4);
        v.x = fmaf(v.x, g_scale[128 + c + 0], g_shift[128 + c + 0]);
        v.y = fmaf(v.y, g_scale[128 + c + 1], g_shift[128 + c + 1]);
        v.z = fmaf(v.z, g_scale[128 + c + 2], g_shift[128 + c + 2]);
        v.w = fmaf(v.w, g_scale[128 + c + 3], g_shift[128 + c + 3]);
        *(float4*)(out + i4) = v;
    }
}

// ---------------- launch -----------------------------------------------------
extern "C" void kernel_launch(void* const* d_in, const int* in_sizes, int n_in,
                              void* d_out, int out_size) {
    const float* x    = (const float*)d_in[0];
    const int*   ei   = (const int*)d_in[1];
    const float* eatt = (const float*)d_in[2];
    const float* W0   = (const float*)d_in[3];
    const float* as0  = (const float*)d_in[4];
    const float* ad0  = (const float*)d_in[5];
    const float* We0  = (const float*)d_in[6];
    const float* ae0  = (const float*)d_in[7];
    const float* b0   = (const float*)d_in[8];
    const float* W1   = (const float*)d_in[9];
    const float* as1  = (const float*)d_in[10];
    const float* ad1  = (const float*)d_in[11];
    const float* We1  = (const float*)d_in[12];
    const float* ae1  = (const float*)d_in[13];
    const float* b1   = (const float*)d_in[14];
    const float* bng  = (const float*)d_in[15];
    const float* bnb  = (const float*)d_in[16];
    const float* bfg  = (const float*)d_in[17];
    const float* bfb  = (const float*)d_in[18];
    float* out = (float*)d_out;

    const int* src = ei;
    const int* dst = ei + EE;

    float* p_xs = nullptr;
    float* p_h  = nullptr;
    cudaGetSymbolAddress((void**)&p_xs, g_xs);
    cudaGetSymbolAddress((void**)&p_h,  g_h);

    static cudaStream_t s1 = nullptr;
    static cudaEvent_t evFork = nullptr, evJoin = nullptr;
    if (!s1) {
        cudaStreamCreateWithFlags(&s1, cudaStreamNonBlocking);
        cudaEventCreateWithFlags(&evFork, cudaEventDisableTiming);
        cudaEventCreateWithFlags(&evJoin, cudaEventDisableTiming);
    }

    const int TB = 256;
    const int gE = (EE + TB - 1) / TB;
    const int gW = (NN * 32 + TB - 1) / TB;
    const int gG = (NN + 127) / 128;

    // ---- fork: ced + CSR build on s1, concurrent with gemm0 on main stream
    cudaEventRecord(evFork, 0);
    cudaStreamWaitEvent(s1, evFork, 0);

    k_ced<<<1, 32, 0, s1>>>(We0, ae0, We1, ae1);
    k_hist<<<gE, TB, 0, s1>>>(dst);
    k_scan_part<<<NBLK, 1024, 0, s1>>>();
    k_scan_apply<<<NBLK, 1024, 0, s1>>>();
    k_scatter<<<gE, TB, 0, s1>>>(src, dst);
    cudaEventRecord(evJoin, s1);

    k_gemm<128, false><<<gG, 256>>>(x, W0, as0, ad0, p_xs);

    cudaStreamWaitEvent(0, evJoin, 0);

    // ---- layer 0 (BN finalize fused into agg)
    k_alphaF<<<gE, TB>>>(eatt, src, dst);
    k_agg<128, false><<<gW, TB>>>(b0, p_h, bng, bnb, 0, 0, 0);

    // ---- layer 1 (BN+relu fused into A-load; alpha inline; BN fused)
    k_gemm<112, true><<<gG, 256>>>(p_h, W1, as1, ad1, p_xs);
    k_agg<112, true><<<gW, TB>>>(b1, p_h, bfg, bfb, 256, 128, 1);
    k_out<<<(NN * 112 / 4 + TB - 1) / TB, TB>>>(p_h, out);
}